// round 1
// baseline (speedup 1.0000x reference)
#include <cuda_runtime.h>
#include <math.h>

#define L_TOK 4096
#define D_DIM 2048

// first 8 POS_MASS_WEIGHTS
__constant__ float c_posw[8] = {0.95f, 0.9f, 0.85f, 0.5f, 0.4f, 0.2f, 0.15f, 0.05f};

// ---- scratch (no allocations allowed -> __device__ globals) ----
__device__ float g_mass[L_TOK];
__device__ float g_bh[L_TOK];
__device__ float g_kpi[L_TOK];
__device__ float g_slot[L_TOK];
__device__ float g_depthf[L_TOK];
__device__ int   g_pidx[L_TOK];
__device__ int   g_coll[L_TOK];
__device__ float g_sg[64];
__device__ float g_sgmacro;
__device__ float g_invT;
__device__ float g_V[(size_t)L_TOK * D_DIM];   // 32 MB
__device__ float g_AV[(size_t)L_TOK * D_DIM];  // 32 MB

// ---------------------------------------------------------------------------
// Kernel 1: per-token precompute (row norms, masses, bh force, sigmoids)
// ---------------------------------------------------------------------------
__global__ void __launch_bounds__(256) precompute_kernel(
    const float* __restrict__ tv, const int* __restrict__ pos,
    const int* __restrict__ dep, const int* __restrict__ slot,
    const float* __restrict__ conf, const float* __restrict__ res,
    const float* __restrict__ kspr)
{
    int row = blockIdx.x;
    const float4* v4 = (const float4*)(tv + (size_t)row * D_DIM);
    float s = 0.f;
    for (int i = threadIdx.x; i < D_DIM / 4; i += blockDim.x) {
        float4 v = v4[i];
        s += v.x * v.x + v.y * v.y + v.z * v.z + v.w * v.w;
    }
    __shared__ float sh[8];
    #pragma unroll
    for (int o = 16; o; o >>= 1) s += __shfl_xor_sync(0xffffffffu, s, o);
    if ((threadIdx.x & 31) == 0) sh[threadIdx.x >> 5] = s;
    __syncthreads();
    if (threadIdx.x == 0) {
        float tot = 0.f;
        #pragma unroll
        for (int i = 0; i < 8; i++) tot += sh[i];
        float norm = sqrtf(tot);
        int p = pos[row] & 7;      // pos_idx % 8 (values are non-negative)
        g_pidx[row] = p;
        g_mass[row] = norm * c_posw[p] * (1.f + res[row]);
        float cf = conf[row];
        float gap = fmaxf(cf - 0.1f, 1e-6f);
        bool c = (cf <= 0.1f);
        g_bh[row] = c ? -1e6f : (-0.01f / (gap * gap));
        g_coll[row] = c ? 1 : 0;
        g_kpi[row] = 1.f / (1.f + expf(-kspr[p]));
        g_slot[row] = (float)slot[row];
        g_depthf[row] = (float)dep[row];
    }
}

// ---------------------------------------------------------------------------
// Kernel 2: tiny tables (sigmoid(G_micro), sigmoid(G_macro), 1/T)
// ---------------------------------------------------------------------------
__global__ void prep_tables_kernel(const float* __restrict__ Gm,
                                   const float* __restrict__ GM,
                                   const float* __restrict__ temp)
{
    int t = threadIdx.x;
    if (t < 64) g_sg[t] = 1.f / (1.f + expf(-Gm[t]));
    if (t == 64) g_sgmacro = 1.f / (1.f + expf(-GM[0]));
    if (t == 65) {
        float T = fmaxf(fabsf(temp[0]), 0.1f);
        g_invT = 1.f / T;
    }
}

// ---------------------------------------------------------------------------
// Kernel 3: scores (L x L)
// ---------------------------------------------------------------------------
__global__ void __launch_bounds__(256) scores_kernel(
    const float* __restrict__ tpos, float* __restrict__ S)
{
    int j = blockIdx.x * 32 + threadIdx.x;
    int i = blockIdx.y * 8 + threadIdx.y;
    float mi = g_mass[i], mj = g_mass[j];
    float mm = mi * mj;
    int pi = g_pidx[i], pj = g_pidx[j];
    float sgk = g_sg[pi * 8 + pj];
    float sd = fmaxf(fabsf(g_slot[i] - g_slot[j]), 1.0f);
    float f = sgk * mm / (sd * sd);
    float dd = fabsf(g_depthf[i] - g_depthf[j]) + 1.0f;
    f += g_sgmacro * mm / (dd * dd);
    f += g_kpi[i] * fabsf(tpos[i] - tpos[j]);
    f += g_bh[i] + g_bh[j];
    if (g_coll[i]) f = -1e6f;
    if (i == j) f = 0.f;
    S[(size_t)i * L_TOK + j] = f;
}

// ---------------------------------------------------------------------------
// Kernel 4: row softmax of scores/T -> A   (one block per row, regs hold row)
// ---------------------------------------------------------------------------
__global__ void __launch_bounds__(256) softmax_kernel(
    const float* __restrict__ S, float* __restrict__ A)
{
    int row = blockIdx.x;
    int t = threadIdx.x;
    const float4* s4 = (const float4*)(S + (size_t)row * L_TOK);
    float4* a4 = (float4*)(A + (size_t)row * L_TOK);
    float4 v[4];
    float mx = -1e30f;
    #pragma unroll
    for (int u = 0; u < 4; u++) {
        v[u] = s4[t + u * 256];
        mx = fmaxf(mx, fmaxf(fmaxf(v[u].x, v[u].y), fmaxf(v[u].z, v[u].w)));
    }
    __shared__ float sh[8];
    __shared__ float sbc;
    #pragma unroll
    for (int o = 16; o; o >>= 1) mx = fmaxf(mx, __shfl_xor_sync(0xffffffffu, mx, o));
    if ((t & 31) == 0) sh[t >> 5] = mx;
    __syncthreads();
    if (t < 8) {
        float x = sh[t];
        #pragma unroll
        for (int o = 4; o; o >>= 1) x = fmaxf(x, __shfl_xor_sync(0xffu, x, o));
        if (t == 0) sbc = x;
    }
    __syncthreads();
    mx = sbc;
    float invT = g_invT;
    float sum = 0.f;
    #pragma unroll
    for (int u = 0; u < 4; u++) {
        v[u].x = __expf((v[u].x - mx) * invT);
        v[u].y = __expf((v[u].y - mx) * invT);
        v[u].z = __expf((v[u].z - mx) * invT);
        v[u].w = __expf((v[u].w - mx) * invT);
        sum += v[u].x + v[u].y + v[u].z + v[u].w;
    }
    __syncthreads();
    #pragma unroll
    for (int o = 16; o; o >>= 1) sum += __shfl_xor_sync(0xffffffffu, sum, o);
    if ((t & 31) == 0) sh[t >> 5] = sum;
    __syncthreads();
    if (t < 8) {
        float x = sh[t];
        #pragma unroll
        for (int o = 4; o; o >>= 1) x += __shfl_xor_sync(0xffu, x, o);
        if (t == 0) sbc = x;
    }
    __syncthreads();
    float r = 1.f / sbc;
    #pragma unroll
    for (int u = 0; u < 4; u++) {
        v[u].x *= r; v[u].y *= r; v[u].z *= r; v[u].w *= r;
        a4[t + u * 256] = v[u];
    }
}

// ---------------------------------------------------------------------------
// Kernel 5: SGEMM  C[M,N] = A[M,K] * op(B) + bias
//   TRANSB=true : B is [N,K] row-major (C = A * B^T)
//   TRANSB=false: B is [K,N] row-major (C = A * B)
// 128x128 tile, BK=16, 8x8 per thread, 256 threads.
// ---------------------------------------------------------------------------
template <bool TRANSB>
__global__ void __launch_bounds__(256) sgemm_kernel(
    const float* __restrict__ A, const float* __restrict__ B,
    const float* __restrict__ bias, float* __restrict__ C,
    int M, int N, int K)
{
    __shared__ float As[16][132];
    __shared__ float Bs[16][132];
    const int tid = threadIdx.x;
    const int tx = tid & 15, ty = tid >> 4;
    const int brow = blockIdx.y * 128, bcol = blockIdx.x * 128;
    const int lrow = tid >> 2, lcol = (tid & 3) * 4;   // 128x16 tile loads
    const int nrow = tid >> 5, ncol = (tid & 31) * 4;  // 16x128 tile loads
    float acc[8][8] = {};

    for (int k0 = 0; k0 < K; k0 += 16) {
        #pragma unroll
        for (int r = 0; r < 2; r++) {
            float4 va = *(const float4*)(A + (size_t)(brow + lrow + r * 64) * K + k0 + lcol);
            As[lcol + 0][lrow + r * 64] = va.x;
            As[lcol + 1][lrow + r * 64] = va.y;
            As[lcol + 2][lrow + r * 64] = va.z;
            As[lcol + 3][lrow + r * 64] = va.w;
        }
        if (TRANSB) {
            #pragma unroll
            for (int r = 0; r < 2; r++) {
                float4 vb = *(const float4*)(B + (size_t)(bcol + lrow + r * 64) * K + k0 + lcol);
                Bs[lcol + 0][lrow + r * 64] = vb.x;
                Bs[lcol + 1][lrow + r * 64] = vb.y;
                Bs[lcol + 2][lrow + r * 64] = vb.z;
                Bs[lcol + 3][lrow + r * 64] = vb.w;
            }
        } else {
            #pragma unroll
            for (int r = 0; r < 2; r++) {
                float4 vb = *(const float4*)(B + (size_t)(k0 + nrow + r * 8) * N + bcol + ncol);
                *(float4*)&Bs[nrow + r * 8][ncol] = vb;
            }
        }
        __syncthreads();
        #pragma unroll
        for (int kk = 0; kk < 16; kk++) {
            float ra[8], rb[8];
            *(float4*)&ra[0] = *(const float4*)&As[kk][ty * 8];
            *(float4*)&ra[4] = *(const float4*)&As[kk][ty * 8 + 4];
            *(float4*)&rb[0] = *(const float4*)&Bs[kk][tx * 8];
            *(float4*)&rb[4] = *(const float4*)&Bs[kk][tx * 8 + 4];
            #pragma unroll
            for (int i = 0; i < 8; i++)
                #pragma unroll
                for (int j = 0; j < 8; j++)
                    acc[i][j] += ra[i] * rb[j];
        }
        __syncthreads();
    }

    #pragma unroll
    for (int i = 0; i < 8; i++) {
        size_t row = brow + ty * 8 + i;
        #pragma unroll
        for (int j = 0; j < 8; j += 4) {
            int col = bcol + tx * 8 + j;
            float4 o;
            o.x = acc[i][j + 0];
            o.y = acc[i][j + 1];
            o.z = acc[i][j + 2];
            o.w = acc[i][j + 3];
            if (bias) {
                o.x += bias[col + 0];
                o.y += bias[col + 1];
                o.z += bias[col + 2];
                o.w += bias[col + 3];
            }
            *(float4*)(C + row * N + col) = o;
        }
    }
}

// ---------------------------------------------------------------------------
// launch
// ---------------------------------------------------------------------------
extern "C" void kernel_launch(void* const* d_in, const int* in_sizes, int n_in,
                              void* d_out, int out_size)
{
    const float* token_vecs = (const float*)d_in[0];
    const int*   pos_idx    = (const int*)  d_in[1];
    const int*   depth      = (const int*)  d_in[2];
    const int*   slot_idx   = (const int*)  d_in[3];
    const float* token_pos  = (const float*)d_in[4];
    const float* conf       = (const float*)d_in[5];
    const float* reso       = (const float*)d_in[6];
    const float* G_micro    = (const float*)d_in[7];
    const float* G_macro    = (const float*)d_in[8];
    const float* k_spring   = (const float*)d_in[9];
    const float* temperature= (const float*)d_in[10];
    const float* Wv_w       = (const float*)d_in[11];
    const float* Wv_b       = (const float*)d_in[12];
    const float* Wout_w     = (const float*)d_in[13];
    const float* Wout_b     = (const float*)d_in[14];

    float* out   = (float*)d_out;                               // [L, d]
    float* Amat  = out  + (size_t)L_TOK * D_DIM;                // [L, L]
    float* Smat  = Amat + (size_t)L_TOK * L_TOK;                // [L, L]

    float *pV = nullptr, *pAV = nullptr;
    cudaGetSymbolAddress((void**)&pV, g_V);
    cudaGetSymbolAddress((void**)&pAV, g_AV);

    // per-token scalars + tables
    precompute_kernel<<<L_TOK, 256>>>(token_vecs, pos_idx, depth, slot_idx,
                                      conf, reso, k_spring);
    prep_tables_kernel<<<1, 128>>>(G_micro, G_macro, temperature);

    // scores and softmax
    {
        dim3 blk(32, 8);
        dim3 grd(L_TOK / 32, L_TOK / 8);
        scores_kernel<<<grd, blk>>>(token_pos, Smat);
    }
    softmax_kernel<<<L_TOK, 256>>>(Smat, Amat);

    // V = X @ Wv^T + b
    {
        dim3 grd(D_DIM / 128, L_TOK / 128);
        sgemm_kernel<true><<<grd, 256>>>(token_vecs, Wv_w, Wv_b, pV,
                                         L_TOK, D_DIM, D_DIM);
    }
    // AV = A @ V
    {
        dim3 grd(D_DIM / 128, L_TOK / 128);
        sgemm_kernel<false><<<grd, 256>>>(Amat, pV, nullptr, pAV,
                                          L_TOK, D_DIM, L_TOK);
    }
    // out = AV @ Wout^T + b
    {
        dim3 grd(D_DIM / 128, L_TOK / 128);
        sgemm_kernel<true><<<grd, 256>>>(pAV, Wout_w, Wout_b, out,
                                         L_TOK, D_DIM, D_DIM);
    }
}

// round 4
// speedup vs baseline: 3.3830x; 3.3830x over previous
#include <cuda_runtime.h>
#include <cuda_fp16.h>
#include <math.h>
#include <stdint.h>

#define L_TOK 4096
#define D_DIM 2048

__constant__ float c_posw[8] = {0.95f, 0.9f, 0.85f, 0.5f, 0.4f, 0.2f, 0.15f, 0.05f};

// ---- scratch (no allocations allowed -> __device__ globals) ----
__device__ float4 g_pk[L_TOK];          // {mass, bh, slot_f, (pidx | depth<<3)}
__device__ float  g_kpi[L_TOK];
__device__ int    g_coll[L_TOK];
__device__ float  g_sg[64];
__device__ float  g_sgmacro;
__device__ float  g_invT;

__device__ __half g_Xh[(size_t)L_TOK * D_DIM];   // 16MB
__device__ __half g_Xl[(size_t)L_TOK * D_DIM];   // 16MB
__device__ __half g_Wvh[(size_t)D_DIM * D_DIM];  // 8MB
__device__ __half g_Wouth[(size_t)D_DIM * D_DIM];// 8MB
__device__ float  g_V[(size_t)L_TOK * D_DIM];    // 32MB
__device__ __half g_Vth[(size_t)D_DIM * L_TOK];  // 16MB (V^T hi)
__device__ __half g_Ahm[(size_t)L_TOK * L_TOK];  // 32MB
__device__ __half g_Alm[(size_t)L_TOK * L_TOK];  // 32MB
__device__ __half g_AVh[(size_t)L_TOK * D_DIM];  // 16MB
__device__ __half g_AVl[(size_t)L_TOK * D_DIM];  // 16MB

// ===========================================================================
// PTX helpers (all sm_80-era -> valid on compute_103)
// ===========================================================================
static __device__ __forceinline__ uint32_t su32(const void* p) {
    uint32_t a;
    asm("{ .reg .u64 t; cvta.to.shared.u64 t, %1; cvt.u32.u64 %0, t; }"
        : "=r"(a) : "l"(p));
    return a;
}
#define CP16(sm, gm) \
    asm volatile("cp.async.cg.shared.global [%0], [%1], 16;" :: "r"(sm), "l"(gm))
#define CP_COMMIT() asm volatile("cp.async.commit_group;")
#define CP_WAIT2()  asm volatile("cp.async.wait_group 2;")
#define LDSM4(r, a) \
    asm volatile("ldmatrix.sync.aligned.m8n8.x4.shared.b16 {%0,%1,%2,%3}, [%4];" \
                 : "=r"((r)[0]), "=r"((r)[1]), "=r"((r)[2]), "=r"((r)[3]) : "r"(a))
#define MMA16816(d, a, b0, b1) \
    asm volatile("mma.sync.aligned.m16n8k16.row.col.f32.f16.f16.f32 " \
                 "{%0,%1,%2,%3}, {%4,%5,%6,%7}, {%8,%9}, {%0,%1,%2,%3};" \
                 : "+f"((d)[0]), "+f"((d)[1]), "+f"((d)[2]), "+f"((d)[3]) \
                 : "r"((a)[0]), "r"((a)[1]), "r"((a)[2]), "r"((a)[3]), "r"(b0), "r"(b1))

// ===========================================================================
// Kernel 1: per-token precompute
// ===========================================================================
__global__ void __launch_bounds__(256) precompute_kernel(
    const float* __restrict__ tv, const int* __restrict__ pos,
    const int* __restrict__ dep, const int* __restrict__ slot,
    const float* __restrict__ conf, const float* __restrict__ res,
    const float* __restrict__ kspr)
{
    int row = blockIdx.x;
    const float4* v4 = (const float4*)(tv + (size_t)row * D_DIM);
    float s = 0.f;
    for (int i = threadIdx.x; i < D_DIM / 4; i += blockDim.x) {
        float4 v = v4[i];
        s += v.x * v.x + v.y * v.y + v.z * v.z + v.w * v.w;
    }
    __shared__ float sh[8];
    #pragma unroll
    for (int o = 16; o; o >>= 1) s += __shfl_xor_sync(0xffffffffu, s, o);
    if ((threadIdx.x & 31) == 0) sh[threadIdx.x >> 5] = s;
    __syncthreads();
    if (threadIdx.x == 0) {
        float tot = 0.f;
        #pragma unroll
        for (int i = 0; i < 8; i++) tot += sh[i];
        float norm = sqrtf(tot);
        int p = pos[row] & 7;
        int d = dep[row];
        float mass = norm * c_posw[p] * (1.f + res[row]);
        float cf = conf[row];
        float gap = fmaxf(cf - 0.1f, 1e-6f);
        bool c = (cf <= 0.1f);
        float bh = c ? -1e6f : (-0.01f / (gap * gap));
        g_pk[row] = make_float4(mass, bh, (float)slot[row], (float)(p | (d << 3)));
        g_coll[row] = c ? 1 : 0;
        g_kpi[row] = 1.f / (1.f + expf(-kspr[p]));
    }
}

__global__ void prep_tables_kernel(const float* __restrict__ Gm,
                                   const float* __restrict__ GM,
                                   const float* __restrict__ temp)
{
    int t = threadIdx.x;
    if (t < 64) g_sg[t] = 1.f / (1.f + expf(-Gm[t]));
    if (t == 64) g_sgmacro = 1.f / (1.f + expf(-GM[0]));
    if (t == 65) g_invT = 1.f / fmaxf(fabsf(temp[0]), 0.1f);
}

// ===========================================================================
// Conversion kernels
// ===========================================================================
__global__ void __launch_bounds__(256) convert_split_kernel(
    const float* __restrict__ src, __half* __restrict__ h, __half* __restrict__ l)
{
    int i = blockIdx.x * 256 + threadIdx.x;
    float4 v = ((const float4*)src)[i];
    __half hx = __float2half_rn(v.x), hy = __float2half_rn(v.y);
    __half hz = __float2half_rn(v.z), hw = __float2half_rn(v.w);
    ((__half2*)h)[2 * i + 0] = __halves2half2(hx, hy);
    ((__half2*)h)[2 * i + 1] = __halves2half2(hz, hw);
    ((__half2*)l)[2 * i + 0] = __floats2half2_rn(v.x - __half2float(hx), v.y - __half2float(hy));
    ((__half2*)l)[2 * i + 1] = __floats2half2_rn(v.z - __half2float(hz), v.w - __half2float(hw));
}

__global__ void __launch_bounds__(256) convert_h_kernel(
    const float* __restrict__ src, __half* __restrict__ h)
{
    int i = blockIdx.x * 256 + threadIdx.x;
    float4 v = ((const float4*)src)[i];
    ((__half2*)h)[2 * i + 0] = __floats2half2_rn(v.x, v.y);
    ((__half2*)h)[2 * i + 1] = __floats2half2_rn(v.z, v.w);
}

// V [L][d] fp32 -> Vt [d][L] fp16 (hi)
__global__ void __launch_bounds__(256) transpose_h_kernel(
    const float* __restrict__ V, __half* __restrict__ Vt)
{
    __shared__ float tile[32][33];
    int n0 = blockIdx.x * 32, m0 = blockIdx.y * 32;
    int tx = threadIdx.x & 31, ty = threadIdx.x >> 5;  // 32 x 8
    #pragma unroll
    for (int k = 0; k < 4; k++)
        tile[ty + 8 * k][tx] = V[(size_t)(m0 + ty + 8 * k) * D_DIM + n0 + tx];
    __syncthreads();
    #pragma unroll
    for (int k = 0; k < 4; k++)
        Vt[(size_t)(n0 + ty + 8 * k) * L_TOK + m0 + tx] = __float2half_rn(tile[tx][ty + 8 * k]);
}

// ===========================================================================
// Kernel: fused scores + softmax; also emits fp16 hi/lo of A
// ===========================================================================
__global__ void __launch_bounds__(256) score_softmax_kernel(
    const float* __restrict__ tpos, float* __restrict__ S, float* __restrict__ A)
{
    __shared__ float sh_sg[64], sh_t1[16], sh_t2[8], red[8];
    __shared__ float sbc;
    int row = blockIdx.x, t = threadIdx.x;
    if (t < 64) sh_sg[t] = g_sg[t];
    else if (t < 80) { int k = t - 64; float d = (float)(k < 1 ? 1 : k); sh_t1[k] = 1.f / (d * d); }
    else if (t < 88) { int k = t - 80; float d = (float)(k + 1); sh_t2[k] = 1.f / (d * d); }

    float4 pki = g_pk[row];
    float mi = pki.x, bhi = pki.y, sli = pki.z;
    int code_i = (int)pki.w;
    int pi8 = (code_i & 7) * 8;
    int di = code_i >> 3;
    float kpi = g_kpi[row];
    int colli = g_coll[row];
    float ti = tpos[row];
    float sgM = g_sgmacro;
    __syncthreads();

    const float4* tp4 = (const float4*)tpos;
    float4* s4 = (float4*)(S + (size_t)row * L_TOK);
    float4* a4 = (float4*)(A + (size_t)row * L_TOK);
    __half2* ah2 = (__half2*)(g_Ahm + (size_t)row * L_TOK);
    __half2* al2 = (__half2*)(g_Alm + (size_t)row * L_TOK);

    float4 v[4];
    float mx = -1e30f;
    #pragma unroll
    for (int u = 0; u < 4; u++) {
        int j4 = t + u * 256;
        float4 tj = tp4[j4];
        float tje[4] = {tj.x, tj.y, tj.z, tj.w};
        float sc[4];
        #pragma unroll
        for (int e = 0; e < 4; e++) {
            int j = j4 * 4 + e;
            float4 pk = g_pk[j];
            int code = (int)pk.w;
            float t1 = sh_t1[(int)fabsf(sli - pk.z)];
            int dd = di - (code >> 3);
            float t2 = sh_t2[dd < 0 ? -dd : dd];
            float g = sh_sg[pi8 + (code & 7)] * t1;
            g = fmaf(sgM, t2, g);
            float td = fabsf(ti - tje[e]);
            float base = fmaf(kpi, td, bhi + pk.y);
            float f = fmaf(mi * pk.x, g, base);
            if (colli) f = -1e6f;
            if (j == row) f = 0.f;
            sc[e] = f;
        }
        v[u] = make_float4(sc[0], sc[1], sc[2], sc[3]);
        s4[j4] = v[u];
        mx = fmaxf(mx, fmaxf(fmaxf(sc[0], sc[1]), fmaxf(sc[2], sc[3])));
    }
    #pragma unroll
    for (int o = 16; o; o >>= 1) mx = fmaxf(mx, __shfl_xor_sync(0xffffffffu, mx, o));
    if ((t & 31) == 0) red[t >> 5] = mx;
    __syncthreads();
    if (t < 8) {
        float x = red[t];
        #pragma unroll
        for (int o = 4; o; o >>= 1) x = fmaxf(x, __shfl_xor_sync(0xffu, x, o));
        if (t == 0) sbc = x;
    }
    __syncthreads();
    mx = sbc;
    float invT = g_invT;
    float sum = 0.f;
    #pragma unroll
    for (int u = 0; u < 4; u++) {
        v[u].x = __expf((v[u].x - mx) * invT);
        v[u].y = __expf((v[u].y - mx) * invT);
        v[u].z = __expf((v[u].z - mx) * invT);
        v[u].w = __expf((v[u].w - mx) * invT);
        sum += v[u].x + v[u].y + v[u].z + v[u].w;
    }
    __syncthreads();
    #pragma unroll
    for (int o = 16; o; o >>= 1) sum += __shfl_xor_sync(0xffffffffu, sum, o);
    if ((t & 31) == 0) red[t >> 5] = sum;
    __syncthreads();
    if (t < 8) {
        float x = red[t];
        #pragma unroll
        for (int o = 4; o; o >>= 1) x += __shfl_xor_sync(0xffu, x, o);
        if (t == 0) sbc = x;
    }
    __syncthreads();
    float r = 1.f / sbc;
    #pragma unroll
    for (int u = 0; u < 4; u++) {
        v[u].x *= r; v[u].y *= r; v[u].z *= r; v[u].w *= r;
        int j4 = t + u * 256;
        a4[j4] = v[u];
        __half hx = __float2half_rn(v[u].x), hy = __float2half_rn(v[u].y);
        __half hz = __float2half_rn(v[u].z), hw = __float2half_rn(v[u].w);
        ah2[2 * j4 + 0] = __halves2half2(hx, hy);
        ah2[2 * j4 + 1] = __halves2half2(hz, hw);
        al2[2 * j4 + 0] = __floats2half2_rn(v[u].x - __half2float(hx), v[u].y - __half2float(hy));
        al2[2 * j4 + 1] = __floats2half2_rn(v[u].z - __half2float(hz), v[u].w - __half2float(hw));
    }
}

// ===========================================================================
// HMMA GEMM: C[M,N] = (Ah + Al) @ Bh^T   (A [M,K], B [N,K], both K-major fp16)
// CTA 128x128, BK=32, 4-stage cp.async pipeline, 8 warps (32x64 each).
// MODE 0: Cf = acc + bias (fp32).  MODE 1: Ch/Cl = fp16 hi/lo split of acc.
// ===========================================================================
#define STAGES 4
#define RGN 10240              // bytes per operand region (128 rows * 80B)
#define STAGE_BYTES (3 * RGN)  // Ah | Al | Bh
#define GEMM_SMEM (STAGES * STAGE_BYTES)

template <int MODE>
__global__ void __launch_bounds__(256, 1) hmma_gemm_kernel(
    const __half* __restrict__ Ah, const __half* __restrict__ Al,
    const __half* __restrict__ Bh, const float* __restrict__ bias,
    float* __restrict__ Cf, __half* __restrict__ Ch, __half* __restrict__ Cl,
    int K, int lda, int ldb, int ldc)
{
    extern __shared__ char smem[];
    uint32_t sbase = su32(smem);
    int tid = threadIdx.x, lane = tid & 31, warp = tid >> 5;
    int wm0 = (warp & 3) * 32, wn0 = (warp >> 2) * 64;
    int brow = blockIdx.y * 128, bcol = blockIdx.x * 128;

    // per-thread cp.async source/dest (rows tid>>2 and +64, 16B chunk tid&3)
    int lrow = tid >> 2;
    int kc8 = (tid & 3) * 8;
    const __half* gA  = Ah + (size_t)(brow + lrow) * lda + kc8;
    const __half* gAl = Al + (size_t)(brow + lrow) * lda + kc8;
    const __half* gB  = Bh + (size_t)(bcol + lrow) * ldb + kc8;
    size_t stpA = (size_t)64 * lda;  // halfs for +64 rows
    size_t stpB = (size_t)64 * ldb;
    uint32_t so = (uint32_t)(lrow * 80 + (tid & 3) * 16);

    float acc[2][8][4];
    #pragma unroll
    for (int t = 0; t < 2; t++)
        #pragma unroll
        for (int p = 0; p < 8; p++)
            #pragma unroll
            for (int q = 0; q < 4; q++) acc[t][p][q] = 0.f;

    const int nk = K >> 5;

    #pragma unroll
    for (int s = 0; s < STAGES - 1; s++) {
        uint32_t st = sbase + s * STAGE_BYTES;
        int ko = s * 32;
        CP16(st + so,                  gA + ko);
        CP16(st + so + 64 * 80,        gA + ko + stpA);
        CP16(st + RGN + so,            gAl + ko);
        CP16(st + RGN + so + 64 * 80,  gAl + ko + stpA);
        CP16(st + 2 * RGN + so,           gB + ko);
        CP16(st + 2 * RGN + so + 64 * 80, gB + ko + stpB);
        CP_COMMIT();
    }

    uint32_t a_off = (uint32_t)((wm0 + (lane & 15)) * 80 + (lane >> 4) * 16);
    uint32_t b_off = (uint32_t)(2 * RGN +
                     (wn0 + (lane & 7) + ((lane >> 4) & 1) * 8) * 80 +
                     ((lane >> 3) & 1) * 16);

    for (int kt = 0; kt < nk; kt++) {
        CP_WAIT2();
        __syncthreads();
        int pf = kt + STAGES - 1;
        if (pf < nk) {
            uint32_t st = sbase + (pf & (STAGES - 1)) * STAGE_BYTES;
            int ko = pf * 32;
            CP16(st + so,                  gA + ko);
            CP16(st + so + 64 * 80,        gA + ko + stpA);
            CP16(st + RGN + so,            gAl + ko);
            CP16(st + RGN + so + 64 * 80,  gAl + ko + stpA);
            CP16(st + 2 * RGN + so,           gB + ko);
            CP16(st + 2 * RGN + so + 64 * 80, gB + ko + stpB);
        }
        CP_COMMIT();

        uint32_t st = sbase + (kt & (STAGES - 1)) * STAGE_BYTES;
        #pragma unroll
        for (int ks = 0; ks < 2; ks++) {
            uint32_t ab = st + a_off + ks * 32;
            uint32_t bb0 = st + b_off + ks * 32;
            uint32_t ah[2][4], al[2][4], bf[4][4];
            LDSM4(ah[0], ab);
            LDSM4(ah[1], ab + 16 * 80);
            LDSM4(al[0], ab + RGN);
            LDSM4(al[1], ab + RGN + 16 * 80);
            #pragma unroll
            for (int p = 0; p < 4; p++) LDSM4(bf[p], bb0 + p * 16 * 80);
            #pragma unroll
            for (int t = 0; t < 2; t++)
                #pragma unroll
                for (int p = 0; p < 4; p++) {
                    MMA16816(acc[t][2 * p],     ah[t], bf[p][0], bf[p][1]);
                    MMA16816(acc[t][2 * p],     al[t], bf[p][0], bf[p][1]);
                    MMA16816(acc[t][2 * p + 1], ah[t], bf[p][2], bf[p][3]);
                    MMA16816(acc[t][2 * p + 1], al[t], bf[p][2], bf[p][3]);
                }
        }
    }

    // epilogue
    #pragma unroll
    for (int t = 0; t < 2; t++) {
        int r0 = brow + wm0 + t * 16 + (lane >> 2);
        #pragma unroll
        for (int p = 0; p < 8; p++) {
            int col = bcol + wn0 + p * 8 + 2 * (lane & 3);
            if (MODE == 0) {
                float bx = bias[col], by = bias[col + 1];
                float2 v01 = make_float2(acc[t][p][0] + bx, acc[t][p][1] + by);
                float2 v23 = make_float2(acc[t][p][2] + bx, acc[t][p][3] + by);
                *(float2*)(Cf + (size_t)r0 * ldc + col) = v01;
                *(float2*)(Cf + (size_t)(r0 + 8) * ldc + col) = v23;
            } else {
                float v0 = acc[t][p][0], v1 = acc[t][p][1];
                float v2 = acc[t][p][2], v3 = acc[t][p][3];
                __half h0 = __float2half_rn(v0), h1 = __float2half_rn(v1);
                __half h2 = __float2half_rn(v2), h3 = __float2half_rn(v3);
                *(__half2*)(Ch + (size_t)r0 * ldc + col) = __halves2half2(h0, h1);
                *(__half2*)(Ch + (size_t)(r0 + 8) * ldc + col) = __halves2half2(h2, h3);
                *(__half2*)(Cl + (size_t)r0 * ldc + col) =
                    __floats2half2_rn(v0 - __half2float(h0), v1 - __half2float(h1));
                *(__half2*)(Cl + (size_t)(r0 + 8) * ldc + col) =
                    __floats2half2_rn(v2 - __half2float(h2), v3 - __half2float(h3));
            }
        }
    }
}

// ===========================================================================
// launch
// ===========================================================================
extern "C" void kernel_launch(void* const* d_in, const int* in_sizes, int n_in,
                              void* d_out, int out_size)
{
    const float* token_vecs = (const float*)d_in[0];
    const int*   pos_idx    = (const int*)  d_in[1];
    const int*   depth      = (const int*)  d_in[2];
    const int*   slot_idx   = (const int*)  d_in[3];
    const float* token_pos  = (const float*)d_in[4];
    const float* conf       = (const float*)d_in[5];
    const float* reso       = (const float*)d_in[6];
    const float* G_micro    = (const float*)d_in[7];
    const float* G_macro    = (const float*)d_in[8];
    const float* k_spring   = (const float*)d_in[9];
    const float* temperature= (const float*)d_in[10];
    const float* Wv_w       = (const float*)d_in[11];
    const float* Wv_b       = (const float*)d_in[12];
    const float* Wout_w     = (const float*)d_in[13];
    const float* Wout_b     = (const float*)d_in[14];

    float* out  = (float*)d_out;                     // [L, d]
    float* Amat = out  + (size_t)L_TOK * D_DIM;      // [L, L]
    float* Smat = Amat + (size_t)L_TOK * L_TOK;      // [L, L]

    __half *pXh, *pXl, *pWvh, *pWouth, *pVth, *pAhm, *pAlm, *pAVh, *pAVl;
    float  *pV;
    cudaGetSymbolAddress((void**)&pXh, g_Xh);
    cudaGetSymbolAddress((void**)&pXl, g_Xl);
    cudaGetSymbolAddress((void**)&pWvh, g_Wvh);
    cudaGetSymbolAddress((void**)&pWouth, g_Wouth);
    cudaGetSymbolAddress((void**)&pV, g_V);
    cudaGetSymbolAddress((void**)&pVth, g_Vth);
    cudaGetSymbolAddress((void**)&pAhm, g_Ahm);
    cudaGetSymbolAddress((void**)&pAlm, g_Alm);
    cudaGetSymbolAddress((void**)&pAVh, g_AVh);
    cudaGetSymbolAddress((void**)&pAVl, g_AVl);

    cudaFuncSetAttribute(hmma_gemm_kernel<0>,
                         cudaFuncAttributeMaxDynamicSharedMemorySize, GEMM_SMEM);
    cudaFuncSetAttribute(hmma_gemm_kernel<1>,
                         cudaFuncAttributeMaxDynamicSharedMemorySize, GEMM_SMEM);

    precompute_kernel<<<L_TOK, 256>>>(token_vecs, pos_idx, depth, slot_idx,
                                      conf, reso, k_spring);
    prep_tables_kernel<<<1, 128>>>(G_micro, G_macro, temperature);

    // fp16 conversions
    convert_split_kernel<<<(L_TOK * D_DIM / 4) / 256, 256>>>(token_vecs, pXh, pXl);
    convert_h_kernel<<<(D_DIM * D_DIM / 4) / 256, 256>>>(Wv_w, pWvh);
    convert_h_kernel<<<(D_DIM * D_DIM / 4) / 256, 256>>>(Wout_w, pWouth);

    // scores + softmax (+ fp16 split of A)
    score_softmax_kernel<<<L_TOK, 256>>>(token_pos, Smat, Amat);

    dim3 grd(D_DIM / 128, L_TOK / 128);   // (16, 32)
    // V = X @ Wv^T + b   (fp32 out)
    hmma_gemm_kernel<0><<<grd, 256, GEMM_SMEM>>>(
        pXh, pXl, pWvh, Wv_b, pV, nullptr, nullptr, D_DIM, D_DIM, D_DIM, D_DIM);
    // Vt (fp16 hi) = V^T
    transpose_h_kernel<<<dim3(D_DIM / 32, L_TOK / 32), 256>>>(pV, pVth);
    // AV = A @ V  (fp16 hi/lo out)
    hmma_gemm_kernel<1><<<grd, 256, GEMM_SMEM>>>(
        pAhm, pAlm, pVth, nullptr, nullptr, pAVh, pAVl, L_TOK, L_TOK, L_TOK, D_DIM);
    // out = AV @ Wout^T + b  (fp32 out)
    hmma_gemm_kernel<0><<<grd, 256, GEMM_SMEM>>>(
        pAVh, pAVl, pWouth, Wout_b, out, nullptr, nullptr, D_DIM, D_DIM, D_DIM, D_DIM);
}